// round 2
// baseline (speedup 1.0000x reference)
#include <cuda_runtime.h>
#include <math.h>

// Problem constants
#define Bb   4
#define Ss   2048
#define HIDc 2048
#define Hh   16
#define Dd   128
#define QKVO 6144   // (H + 2H) * D

// Scratch buffers (static device globals: allocation-free per harness rules)
static __device__ float g_qkv[(size_t)Bb * Ss * QKVO];       // 192 MB: [8192, 6144] (q|k|v)
static __device__ float g_scores[(size_t)Bb * Hh * Ss * Ss]; // 1 GB:   [b,h,q,k]
static __device__ float g_attn[(size_t)Bb * Ss * HIDc];      // 64 MB:  [8192, 2048]

// Resolve scratch-buffer selectors inside device code (avoids any host-side
// symbol-address API during graph capture).
__device__ __forceinline__ float* resolve_buf(const float* ext, int sel) {
    switch (sel) {
        case 1: return g_qkv;
        case 2: return g_scores;
        case 3: return g_attn;
        default: return const_cast<float*>(ext);
    }
}

// ---------------------------------------------------------------------------
// SGEMM NN: C[M,N] = A[M,K] (row-major, lda) * B[K,N] (row-major, ldb)
// 128x128 block, BK=8, 256 threads, 8x8 per-thread micro-tile.
// Double-buffered smem: global loads of tile k+1 overlap compute of tile k,
// one __syncthreads per K-step.
// blockIdx.z decomposed as (b, h) with per-operand strides for batched use.
// ---------------------------------------------------------------------------
__global__ __launch_bounds__(256)
void sgemm_nn_kernel(const float* Aext, int selA, long long offA,
                     const float* Bext, int selB, long long offB,
                     float* Cext, int selC, long long offC,
                     int M, int N, int K, int lda, int ldb, int ldc,
                     long long sAb, long long sAh,
                     long long sBb, long long sBh,
                     long long sCb, long long sCh, int Hn)
{
    const int z = blockIdx.z;
    const int b = z / Hn;
    const int h = z - b * Hn;
    const float* A = resolve_buf(Aext, selA) + offA + (long long)b * sAb + (long long)h * sAh;
    const float* B = resolve_buf(Bext, selB) + offB + (long long)b * sBb + (long long)h * sBh;
    float*       C = resolve_buf(Cext, selC) + offC + (long long)b * sCb + (long long)h * sCh;

    __shared__ float As[2][8][128];   // transposed A tile: As[buf][k][m]
    __shared__ float Bs[2][8][128];   // Bs[buf][k][n]

    const int tid  = threadIdx.x;
    const int tx   = tid & 15;     // column group
    const int ty   = tid >> 4;     // row group
    const int row0 = blockIdx.y * 128;
    const int col0 = blockIdx.x * 128;

    // A tile load mapping: 128 rows x 8 cols, one float4 per thread
    const int ar = tid >> 1;          // 0..127
    const int ac = (tid & 1) * 4;     // 0 or 4
    // B tile load mapping: 8 rows x 128 cols, one float4 per thread
    const int br = tid >> 5;          // 0..7
    const int bc = (tid & 31) * 4;    // 0..124

    const float* Aptr = A + (long long)(row0 + ar) * lda + ac;
    const float* Bptr = B + (long long)br * ldb + col0 + bc;

    float acc[8][8];
    #pragma unroll
    for (int i = 0; i < 8; i++)
        #pragma unroll
        for (int j = 0; j < 8; j++)
            acc[i][j] = 0.f;

    // Prologue: load tile 0 into buffer 0
    {
        float4 av = *reinterpret_cast<const float4*>(Aptr);
        float4 bv = *reinterpret_cast<const float4*>(Bptr);
        As[0][ac + 0][ar] = av.x;
        As[0][ac + 1][ar] = av.y;
        As[0][ac + 2][ar] = av.z;
        As[0][ac + 3][ar] = av.w;
        *reinterpret_cast<float4*>(&Bs[0][br][bc]) = bv;
    }
    __syncthreads();

    int buf = 0;
    for (int k0 = 0; k0 < K; k0 += 8) {
        // Prefetch next tile into registers (overlaps with compute below)
        float4 av, bv;
        const bool has_next = (k0 + 8 < K);
        if (has_next) {
            av = *reinterpret_cast<const float4*>(Aptr + (k0 + 8));
            bv = *reinterpret_cast<const float4*>(Bptr + (long long)(k0 + 8) * ldb);
        }

        #pragma unroll
        for (int kk = 0; kk < 8; kk++) {
            float4 a0 = *reinterpret_cast<const float4*>(&As[buf][kk][ty * 8]);
            float4 a1 = *reinterpret_cast<const float4*>(&As[buf][kk][ty * 8 + 4]);
            float4 b0 = *reinterpret_cast<const float4*>(&Bs[buf][kk][tx * 8]);
            float4 b1 = *reinterpret_cast<const float4*>(&Bs[buf][kk][tx * 8 + 4]);
            float a[8]  = {a0.x, a0.y, a0.z, a0.w, a1.x, a1.y, a1.z, a1.w};
            float bb[8] = {b0.x, b0.y, b0.z, b0.w, b1.x, b1.y, b1.z, b1.w};
            #pragma unroll
            for (int i = 0; i < 8; i++)
                #pragma unroll
                for (int j = 0; j < 8; j++)
                    acc[i][j] = fmaf(a[i], bb[j], acc[i][j]);
        }

        if (has_next) {
            const int nb = buf ^ 1;
            As[nb][ac + 0][ar] = av.x;
            As[nb][ac + 1][ar] = av.y;
            As[nb][ac + 2][ar] = av.z;
            As[nb][ac + 3][ar] = av.w;
            *reinterpret_cast<float4*>(&Bs[nb][br][bc]) = bv;
            __syncthreads();
            buf = nb;
        }
    }

    #pragma unroll
    for (int i = 0; i < 8; i++) {
        float* Crow = C + (long long)(row0 + ty * 8 + i) * ldc + col0 + tx * 8;
        *reinterpret_cast<float4*>(Crow)     = make_float4(acc[i][0], acc[i][1], acc[i][2], acc[i][3]);
        *reinterpret_cast<float4*>(Crow + 4) = make_float4(acc[i][4], acc[i][5], acc[i][6], acc[i][7]);
    }
}

// ---------------------------------------------------------------------------
// SGEMM NT: C[M,N] = alpha * A[M,K] (row-major) * B[N,K]^T (B row-major, ldb)
// Used for scores = scale * Q @ K^T per (b, h). Same double-buffer scheme.
// ---------------------------------------------------------------------------
__global__ __launch_bounds__(256)
void sgemm_nt_kernel(const float* Aext, int selA, long long offA,
                     const float* Bext, int selB, long long offB,
                     float* Cext, int selC, long long offC,
                     int M, int N, int K, int lda, int ldb, int ldc,
                     long long sAb, long long sAh,
                     long long sBb, long long sBh,
                     long long sCb, long long sCh, int Hn, float alpha)
{
    const int z = blockIdx.z;
    const int b = z / Hn;
    const int h = z - b * Hn;
    const float* A = resolve_buf(Aext, selA) + offA + (long long)b * sAb + (long long)h * sAh;
    const float* B = resolve_buf(Bext, selB) + offB + (long long)b * sBb + (long long)h * sBh;
    float*       C = resolve_buf(Cext, selC) + offC + (long long)b * sCb + (long long)h * sCh;

    __shared__ float As[2][8][128];
    __shared__ float Bs[2][8][128];

    const int tid  = threadIdx.x;
    const int tx   = tid & 15;
    const int ty   = tid >> 4;
    const int row0 = blockIdx.y * 128;
    const int col0 = blockIdx.x * 128;

    const int ar = tid >> 1;
    const int ac = (tid & 1) * 4;
    const int brn = tid >> 1;          // n index 0..127
    const int bck = (tid & 1) * 4;     // k offset 0 or 4

    const float* Aptr = A + (long long)(row0 + ar) * lda + ac;
    const float* Bptr = B + (long long)(col0 + brn) * ldb + bck;

    float acc[8][8];
    #pragma unroll
    for (int i = 0; i < 8; i++)
        #pragma unroll
        for (int j = 0; j < 8; j++)
            acc[i][j] = 0.f;

    // Prologue: tile 0 → buffer 0
    {
        float4 av = *reinterpret_cast<const float4*>(Aptr);
        float4 bv = *reinterpret_cast<const float4*>(Bptr);
        As[0][ac + 0][ar] = av.x;
        As[0][ac + 1][ar] = av.y;
        As[0][ac + 2][ar] = av.z;
        As[0][ac + 3][ar] = av.w;
        Bs[0][bck + 0][brn] = bv.x;
        Bs[0][bck + 1][brn] = bv.y;
        Bs[0][bck + 2][brn] = bv.z;
        Bs[0][bck + 3][brn] = bv.w;
    }
    __syncthreads();

    int buf = 0;
    for (int k0 = 0; k0 < K; k0 += 8) {
        float4 av, bv;
        const bool has_next = (k0 + 8 < K);
        if (has_next) {
            av = *reinterpret_cast<const float4*>(Aptr + (k0 + 8));
            bv = *reinterpret_cast<const float4*>(Bptr + (k0 + 8));
        }

        #pragma unroll
        for (int kk = 0; kk < 8; kk++) {
            float4 a0 = *reinterpret_cast<const float4*>(&As[buf][kk][ty * 8]);
            float4 a1 = *reinterpret_cast<const float4*>(&As[buf][kk][ty * 8 + 4]);
            float4 b0 = *reinterpret_cast<const float4*>(&Bs[buf][kk][tx * 8]);
            float4 b1 = *reinterpret_cast<const float4*>(&Bs[buf][kk][tx * 8 + 4]);
            float a[8]  = {a0.x, a0.y, a0.z, a0.w, a1.x, a1.y, a1.z, a1.w};
            float bb[8] = {b0.x, b0.y, b0.z, b0.w, b1.x, b1.y, b1.z, b1.w};
            #pragma unroll
            for (int i = 0; i < 8; i++)
                #pragma unroll
                for (int j = 0; j < 8; j++)
                    acc[i][j] = fmaf(a[i], bb[j], acc[i][j]);
        }

        if (has_next) {
            const int nb = buf ^ 1;
            As[nb][ac + 0][ar] = av.x;
            As[nb][ac + 1][ar] = av.y;
            As[nb][ac + 2][ar] = av.z;
            As[nb][ac + 3][ar] = av.w;
            Bs[nb][bck + 0][brn] = bv.x;
            Bs[nb][bck + 1][brn] = bv.y;
            Bs[nb][bck + 2][brn] = bv.z;
            Bs[nb][bck + 3][brn] = bv.w;
            __syncthreads();
            buf = nb;
        }
    }

    #pragma unroll
    for (int i = 0; i < 8; i++) {
        float* Crow = C + (long long)(row0 + ty * 8 + i) * ldc + col0 + tx * 8;
        *reinterpret_cast<float4*>(Crow) =
            make_float4(acc[i][0] * alpha, acc[i][1] * alpha, acc[i][2] * alpha, acc[i][3] * alpha);
        *reinterpret_cast<float4*>(Crow + 4) =
            make_float4(acc[i][4] * alpha, acc[i][5] * alpha, acc[i][6] * alpha, acc[i][7] * alpha);
    }
}

// ---------------------------------------------------------------------------
// RoPE (in-place on q and k sections of g_qkv).
// out[d]    = x[d]   * cos[s,d]    - x[d+64] * sin[s,d]       (d < 64)
// out[d+64] = x[d+64]* cos[s,d+64] + x[d]    * sin[s,d+64]
// One thread per (row, mat in {q,k}, head, d<64) pair: 16.78M threads.
// ---------------------------------------------------------------------------
__global__ __launch_bounds__(256)
void rope_kernel(const float* __restrict__ cosp, const float* __restrict__ sinp)
{
    int idx = blockIdx.x * blockDim.x + threadIdx.x;   // < 8192*2048
    int d   = idx & 63;
    int t   = idx >> 6;
    int hh  = t & (Hh - 1);
    t >>= 4;
    int mat = t & 1;    // 0 = q, 1 = k
    t >>= 1;
    int m = t;          // global row 0..8191
    int s = m & (Ss - 1);

    size_t base = (size_t)m * QKVO + (size_t)mat * HIDc + (size_t)hh * Dd;
    float x0 = g_qkv[base + d];
    float x1 = g_qkv[base + d + 64];
    float c0 = cosp[s * Dd + d];
    float c1 = cosp[s * Dd + d + 64];
    float s0 = sinp[s * Dd + d];
    float s1 = sinp[s * Dd + d + 64];
    g_qkv[base + d]      = x0 * c0 - x1 * s0;
    g_qkv[base + d + 64] = x1 * c1 + x0 * s1;
}

// ---------------------------------------------------------------------------
// Row softmax over g_scores, one block (256 threads) per row of length 2048.
// Row held in registers (8 floats/thread): exactly 1 read + 1 write of HBM.
// ---------------------------------------------------------------------------
__global__ __launch_bounds__(256)
void softmax_kernel()
{
    float* p = g_scores + (size_t)blockIdx.x * Ss;
    const int tid = threadIdx.x;
    __shared__ float red[256];

    float v[8];
    float mx = -3.4e38f;
    #pragma unroll
    for (int u = 0; u < 8; u++) {
        v[u] = p[tid + u * 256];
        mx = fmaxf(mx, v[u]);
    }
    red[tid] = mx;
    __syncthreads();
    #pragma unroll
    for (int s2 = 128; s2 > 0; s2 >>= 1) {
        if (tid < s2) red[tid] = fmaxf(red[tid], red[tid + s2]);
        __syncthreads();
    }
    mx = red[0];
    __syncthreads();

    float sum = 0.f;
    #pragma unroll
    for (int u = 0; u < 8; u++) {
        v[u] = __expf(v[u] - mx);
        sum += v[u];
    }
    red[tid] = sum;
    __syncthreads();
    #pragma unroll
    for (int s2 = 128; s2 > 0; s2 >>= 1) {
        if (tid < s2) red[tid] += red[tid + s2];
        __syncthreads();
    }
    float inv = 1.f / red[0];
    #pragma unroll
    for (int u = 0; u < 8; u++)
        p[tid + u * 256] = v[u] * inv;
}

// ---------------------------------------------------------------------------
// kernel_launch: graph-capturable sequence of plain kernel launches.
// Inputs (metadata order): hidden_states, cos, sin, w_qkv, w_o. Output: fp32.
// ---------------------------------------------------------------------------
extern "C" void kernel_launch(void* const* d_in, const int* in_sizes, int n_in,
                              void* d_out, int out_size)
{
    const float* hidden = (const float*)d_in[0];
    const float* cosp   = (const float*)d_in[1];
    const float* sinp   = (const float*)d_in[2];
    const float* w_qkv  = (const float*)d_in[3];
    const float* w_o    = (const float*)d_in[4];
    float* out = (float*)d_out;

    const int M = Bb * Ss;   // 8192

    // 1) QKV projection: g_qkv[8192,6144] = hidden[8192,2048] @ w_qkv[2048,6144]
    {
        dim3 grid(QKVO / 128, M / 128, 1);
        sgemm_nn_kernel<<<grid, 256>>>(hidden, 0, 0, w_qkv, 0, 0, nullptr, 1, 0,
                                       M, QKVO, HIDc, HIDc, QKVO, QKVO,
                                       0, 0, 0, 0, 0, 0, 1);
    }

    // 2) RoPE on q and k sections (in place)
    {
        int total = M * 2 * Hh * 64;   // 16,777,216
        rope_kernel<<<total / 256, 256>>>(cosp, sinp);
    }

    // 3) scores[b,h] = (1/sqrt(D)) * Q_bh[2048,128] @ K_bh[2048,128]^T
    {
        dim3 grid(Ss / 128, Ss / 128, Bb * Hh);
        const float alpha = 1.0f / sqrtf((float)Dd);
        sgemm_nt_kernel<<<grid, 256>>>(nullptr, 1, 0,            // A = q section
                                       nullptr, 1, HIDc,         // B = k section (+2048 cols)
                                       nullptr, 2, 0,            // C = scores
                                       Ss, Ss, Dd,
                                       QKVO, QKVO, Ss,
                                       (long long)Ss * QKVO, Dd,
                                       (long long)Ss * QKVO, Dd,
                                       (long long)Hh * Ss * Ss, (long long)Ss * Ss,
                                       Hh, alpha);
    }

    // 4) softmax over last axis (k), one block per row
    softmax_kernel<<<Bb * Hh * Ss, 256>>>();

    // 5) attn[b,q,h,:] = P_bh[2048,2048] @ V_bh[2048,128]
    {
        dim3 grid(Dd / 128, Ss / 128, Bb * Hh);
        sgemm_nn_kernel<<<grid, 256>>>(nullptr, 2, 0,            // A = scores
                                       nullptr, 1, 2 * HIDc,     // B = v section (+4096 cols)
                                       nullptr, 3, 0,            // C = attn
                                       Ss, Dd, Ss,
                                       Ss, QKVO, HIDc,
                                       (long long)Hh * Ss * Ss, (long long)Ss * Ss,
                                       (long long)Ss * QKVO, Dd,
                                       (long long)Ss * HIDc, Dd,
                                       Hh);
    }

    // 6) output projection: out[8192,2048] = attn[8192,2048] @ w_o[2048,2048]
    {
        dim3 grid(HIDc / 128, M / 128, 1);
        sgemm_nn_kernel<<<grid, 256>>>(nullptr, 3, 0, w_o, 0, 0, out, 0, 0,
                                       M, HIDc, HIDc, HIDc, HIDc, HIDc,
                                       0, 0, 0, 0, 0, 0, 1);
    }
}

// round 5
// speedup vs baseline: 1.8171x; 1.8171x over previous
#include <cuda_runtime.h>
#include <math.h>
#include <stdint.h>

// Problem constants
#define Bb   4
#define Ss   2048
#define HIDc 2048
#define Hh   16
#define Dd   128
#define QKVO 6144   // (H + 2H) * D

// Scratch buffers (static device globals: allocation-free per harness rules)
static __device__ float g_qkv[(size_t)Bb * Ss * QKVO];       // 192 MB: [8192, 6144] (q|k|v)
static __device__ float g_scores[(size_t)Bb * Hh * Ss * Ss]; // 1 GB:   [b,h,q,k]
static __device__ float g_attn[(size_t)Bb * Ss * HIDc];      // 64 MB:  [8192, 2048]

__device__ __forceinline__ float* resolve_buf(const float* ext, int sel) {
    switch (sel) {
        case 1: return g_qkv;
        case 2: return g_scores;
        case 3: return g_attn;
        default: return const_cast<float*>(ext);
    }
}

// fp32 -> tf32 (round-to-nearest) conversion; result kept in 32-bit container
__device__ __forceinline__ uint32_t f2tf32(float x) {
    uint32_t u;
    asm("cvt.rna.tf32.f32 %0, %1;" : "=r"(u) : "f"(x));
    return u;
}

__device__ __forceinline__ void mma_tf32(float c[4],
                                         uint32_t a0, uint32_t a1, uint32_t a2, uint32_t a3,
                                         uint32_t b0, uint32_t b1) {
    asm volatile(
        "mma.sync.aligned.m16n8k8.row.col.f32.tf32.tf32.f32 "
        "{%0,%1,%2,%3}, {%4,%5,%6,%7}, {%8,%9}, {%0,%1,%2,%3};"
        : "+f"(c[0]), "+f"(c[1]), "+f"(c[2]), "+f"(c[3])
        : "r"(a0), "r"(a1), "r"(a2), "r"(a3), "r"(b0), "r"(b1));
}

// ---------------------------------------------------------------------------
// Tensor-core TF32 GEMM.
// C[M,N] = alpha * A[M,K] * op(B),  op(B) = B[K,N] (bTrans=0) or B[N,K]^T (bTrans=1)
// Block 128x128, BK=16, 256 threads = 8 warps in 2x4, warp tile 64x32.
// Fragments are m16n8k8 tf32; smem tiles stored K-outer with ld=136 floats,
// which makes all fragment LDS patterns bank-conflict-free.
// Double-buffered: global loads of tile k+1 overlap MMA on tile k.
// All dims divisible by 128 (M,N) / 16 (K) for this problem — no bounds checks.
// ---------------------------------------------------------------------------
__global__ __launch_bounds__(256)
void mma_gemm_kernel(const float* __restrict__ Aext, int selA, long long offA,
                     const float* __restrict__ Bext, int selB, long long offB,
                     float* __restrict__ Cext, int selC, long long offC,
                     int M, int N, int K, int lda, int ldb, int ldc,
                     long long sAb, long long sAh,
                     long long sBb, long long sBh,
                     long long sCb, long long sCh, int Hn,
                     float alpha, int bTrans)
{
    const int z = blockIdx.z;
    const int b = z / Hn;
    const int h = z - b * Hn;
    const float* A = resolve_buf(Aext, selA) + offA + (long long)b * sAb + (long long)h * sAh;
    const float* B = resolve_buf(Bext, selB) + offB + (long long)b * sBb + (long long)h * sBh;
    float*       C = resolve_buf(Cext, selC) + offC + (long long)b * sCb + (long long)h * sCh;

    // [buf][k][m or n], padded to 136 for conflict-free fragment loads
    __shared__ uint32_t As[2][16][136];
    __shared__ uint32_t Bs[2][16][136];

    const int tid  = threadIdx.x;
    const int lane = tid & 31;
    const int warp = tid >> 5;
    const int wm   = (warp >> 2) * 64;   // warp row origin in tile
    const int wn   = (warp & 3) * 32;    // warp col origin in tile
    const int grp  = lane >> 2;          // 0..7
    const int tig  = lane & 3;           // 0..3

    const int row0 = blockIdx.y * 128;
    const int col0 = blockIdx.x * 128;

    // A load mapping (and NT B): 128 rows x 16 k, 8 consecutive k per thread
    const int ar  = tid & 127;
    const int ac0 = (tid >> 7) * 8;      // 0 or 8
    // NN B load mapping: 16 k-rows x 128 cols, 8 consecutive cols per thread
    const int brr = tid >> 4;            // 0..15
    const int bcc = (tid & 15) * 8;      // 0..120

    const float* Aptr   = A + (long long)(row0 + ar) * lda + ac0;
    const float* BptrNN = B + (long long)brr * ldb + col0 + bcc;
    const float* BptrNT = B + (long long)(col0 + ar) * ldb + ac0;

    float acc[4][4][4];
    #pragma unroll
    for (int mi = 0; mi < 4; mi++)
        #pragma unroll
        for (int ni = 0; ni < 4; ni++)
            #pragma unroll
            for (int r = 0; r < 4; r++)
                acc[mi][ni][r] = 0.f;

    // ---- prologue: load tile 0 into buffer 0 ----
    {
        float4 a0 = *reinterpret_cast<const float4*>(Aptr);
        float4 a1 = *reinterpret_cast<const float4*>(Aptr + 4);
        As[0][ac0 + 0][ar] = f2tf32(a0.x);
        As[0][ac0 + 1][ar] = f2tf32(a0.y);
        As[0][ac0 + 2][ar] = f2tf32(a0.z);
        As[0][ac0 + 3][ar] = f2tf32(a0.w);
        As[0][ac0 + 4][ar] = f2tf32(a1.x);
        As[0][ac0 + 5][ar] = f2tf32(a1.y);
        As[0][ac0 + 6][ar] = f2tf32(a1.z);
        As[0][ac0 + 7][ar] = f2tf32(a1.w);
        if (bTrans) {
            float4 b0 = *reinterpret_cast<const float4*>(BptrNT);
            float4 b1 = *reinterpret_cast<const float4*>(BptrNT + 4);
            Bs[0][ac0 + 0][ar] = f2tf32(b0.x);
            Bs[0][ac0 + 1][ar] = f2tf32(b0.y);
            Bs[0][ac0 + 2][ar] = f2tf32(b0.z);
            Bs[0][ac0 + 3][ar] = f2tf32(b0.w);
            Bs[0][ac0 + 4][ar] = f2tf32(b1.x);
            Bs[0][ac0 + 5][ar] = f2tf32(b1.y);
            Bs[0][ac0 + 6][ar] = f2tf32(b1.z);
            Bs[0][ac0 + 7][ar] = f2tf32(b1.w);
        } else {
            float4 b0 = *reinterpret_cast<const float4*>(BptrNN);
            float4 b1 = *reinterpret_cast<const float4*>(BptrNN + 4);
            uint4 v0 = make_uint4(f2tf32(b0.x), f2tf32(b0.y), f2tf32(b0.z), f2tf32(b0.w));
            uint4 v1 = make_uint4(f2tf32(b1.x), f2tf32(b1.y), f2tf32(b1.z), f2tf32(b1.w));
            *reinterpret_cast<uint4*>(&Bs[0][brr][bcc])     = v0;
            *reinterpret_cast<uint4*>(&Bs[0][brr][bcc + 4]) = v1;
        }
    }
    __syncthreads();

    int buf = 0;
    for (int k0 = 0; k0 < K; k0 += 16) {
        const bool has_next = (k0 + 16 < K);
        float4 pa0, pa1, pb0, pb1;
        if (has_next) {
            pa0 = *reinterpret_cast<const float4*>(Aptr + (k0 + 16));
            pa1 = *reinterpret_cast<const float4*>(Aptr + (k0 + 16) + 4);
            if (bTrans) {
                pb0 = *reinterpret_cast<const float4*>(BptrNT + (k0 + 16));
                pb1 = *reinterpret_cast<const float4*>(BptrNT + (k0 + 16) + 4);
            } else {
                pb0 = *reinterpret_cast<const float4*>(BptrNN + (long long)(k0 + 16) * ldb);
                pb1 = *reinterpret_cast<const float4*>(BptrNN + (long long)(k0 + 16) * ldb + 4);
            }
        }

        // ---- compute on current buffer: two k8 sub-steps ----
        #pragma unroll
        for (int ks = 0; ks < 2; ks++) {
            const int kb = ks * 8;
            uint32_t af[4][4];
            uint32_t bfr[4][2];
            #pragma unroll
            for (int mi = 0; mi < 4; mi++) {
                int m = wm + mi * 16 + grp;
                af[mi][0] = As[buf][kb + tig][m];
                af[mi][1] = As[buf][kb + tig][m + 8];
                af[mi][2] = As[buf][kb + tig + 4][m];
                af[mi][3] = As[buf][kb + tig + 4][m + 8];
            }
            #pragma unroll
            for (int ni = 0; ni < 4; ni++) {
                int n = wn + ni * 8 + grp;
                bfr[ni][0] = Bs[buf][kb + tig][n];
                bfr[ni][1] = Bs[buf][kb + tig + 4][n];
            }
            #pragma unroll
            for (int mi = 0; mi < 4; mi++)
                #pragma unroll
                for (int ni = 0; ni < 4; ni++)
                    mma_tf32(acc[mi][ni],
                             af[mi][0], af[mi][1], af[mi][2], af[mi][3],
                             bfr[ni][0], bfr[ni][1]);
        }

        if (has_next) {
            const int nb = buf ^ 1;
            As[nb][ac0 + 0][ar] = f2tf32(pa0.x);
            As[nb][ac0 + 1][ar] = f2tf32(pa0.y);
            As[nb][ac0 + 2][ar] = f2tf32(pa0.z);
            As[nb][ac0 + 3][ar] = f2tf32(pa0.w);
            As[nb][ac0 + 4][ar] = f2tf32(pa1.x);
            As[nb][ac0 + 5][ar] = f2tf32(pa1.y);
            As[nb][ac0 + 6][ar] = f2tf32(pa1.z);
            As[nb][ac0 + 7][ar] = f2tf32(pa1.w);
            if (bTrans) {
                Bs[nb][ac0 + 0][ar] = f2tf32(pb0.x);
                Bs[nb][ac0 + 1][ar] = f2tf32(pb0.y);
                Bs[nb][ac0 + 2][ar] = f2tf32(pb0.z);
                Bs[nb][ac0 + 3][ar] = f2tf32(pb0.w);
                Bs[nb][ac0 + 4][ar] = f2tf32(pb1.x);
                Bs[nb][ac0 + 5][ar] = f2tf32(pb1.y);
                Bs[nb][ac0 + 6][ar] = f2tf32(pb1.z);
                Bs[nb][ac0 + 7][ar] = f2tf32(pb1.w);
            } else {
                uint4 v0 = make_uint4(f2tf32(pb0.x), f2tf32(pb0.y), f2tf32(pb0.z), f2tf32(pb0.w));
                uint4 v1 = make_uint4(f2tf32(pb1.x), f2tf32(pb1.y), f2tf32(pb1.z), f2tf32(pb1.w));
                *reinterpret_cast<uint4*>(&Bs[nb][brr][bcc])     = v0;
                *reinterpret_cast<uint4*>(&Bs[nb][brr][bcc + 4]) = v1;
            }
            __syncthreads();
            buf = nb;
        }
    }

    // ---- epilogue ----
    #pragma unroll
    for (int mi = 0; mi < 4; mi++) {
        const int r = row0 + wm + mi * 16 + grp;
        #pragma unroll
        for (int ni = 0; ni < 4; ni++) {
            const int c = col0 + wn + ni * 8 + tig * 2;
            float2 v0 = make_float2(acc[mi][ni][0] * alpha, acc[mi][ni][1] * alpha);
            float2 v1 = make_float2(acc[mi][ni][2] * alpha, acc[mi][ni][3] * alpha);
            *reinterpret_cast<float2*>(&C[(long long)r * ldc + c])       = v0;
            *reinterpret_cast<float2*>(&C[(long long)(r + 8) * ldc + c]) = v1;
        }
    }
}

// ---------------------------------------------------------------------------
// RoPE (in-place on q and k sections of g_qkv).
// ---------------------------------------------------------------------------
__global__ __launch_bounds__(256)
void rope_kernel(const float* __restrict__ cosp, const float* __restrict__ sinp)
{
    int idx = blockIdx.x * blockDim.x + threadIdx.x;   // < 8192*2048
    int d   = idx & 63;
    int t   = idx >> 6;
    int hh  = t & (Hh - 1);
    t >>= 4;
    int mat = t & 1;    // 0 = q, 1 = k
    t >>= 1;
    int m = t;          // global row 0..8191
    int s = m & (Ss - 1);

    size_t base = (size_t)m * QKVO + (size_t)mat * HIDc + (size_t)hh * Dd;
    float x0 = g_qkv[base + d];
    float x1 = g_qkv[base + d + 64];
    float c0 = cosp[s * Dd + d];
    float c1 = cosp[s * Dd + d + 64];
    float s0 = sinp[s * Dd + d];
    float s1 = sinp[s * Dd + d + 64];
    g_qkv[base + d]      = x0 * c0 - x1 * s0;
    g_qkv[base + d + 64] = x1 * c1 + x0 * s1;
}

// ---------------------------------------------------------------------------
// Row softmax over g_scores, one block (256 threads) per row of length 2048.
// ---------------------------------------------------------------------------
__global__ __launch_bounds__(256)
void softmax_kernel()
{
    float* p = g_scores + (size_t)blockIdx.x * Ss;
    const int tid = threadIdx.x;
    __shared__ float red[256];

    float v[8];
    float mx = -3.4e38f;
    #pragma unroll
    for (int u = 0; u < 8; u++) {
        v[u] = p[tid + u * 256];
        mx = fmaxf(mx, v[u]);
    }
    red[tid] = mx;
    __syncthreads();
    #pragma unroll
    for (int s2 = 128; s2 > 0; s2 >>= 1) {
        if (tid < s2) red[tid] = fmaxf(red[tid], red[tid + s2]);
        __syncthreads();
    }
    mx = red[0];
    __syncthreads();

    float sum = 0.f;
    #pragma unroll
    for (int u = 0; u < 8; u++) {
        v[u] = __expf(v[u] - mx);
        sum += v[u];
    }
    red[tid] = sum;
    __syncthreads();
    #pragma unroll
    for (int s2 = 128; s2 > 0; s2 >>= 1) {
        if (tid < s2) red[tid] += red[tid + s2];
        __syncthreads();
    }
    float inv = 1.f / red[0];
    #pragma unroll
    for (int u = 0; u < 8; u++)
        p[tid + u * 256] = v[u] * inv;
}

// ---------------------------------------------------------------------------
// kernel_launch
// ---------------------------------------------------------------------------
extern "C" void kernel_launch(void* const* d_in, const int* in_sizes, int n_in,
                              void* d_out, int out_size)
{
    const float* hidden = (const float*)d_in[0];
    const float* cosp   = (const float*)d_in[1];
    const float* sinp   = (const float*)d_in[2];
    const float* w_qkv  = (const float*)d_in[3];
    const float* w_o    = (const float*)d_in[4];
    float* out = (float*)d_out;

    const int M = Bb * Ss;   // 8192

    // 1) QKV projection: g_qkv[8192,6144] = hidden @ w_qkv   (NN)
    {
        dim3 grid(QKVO / 128, M / 128, 1);
        mma_gemm_kernel<<<grid, 256>>>(hidden, 0, 0, w_qkv, 0, 0, nullptr, 1, 0,
                                       M, QKVO, HIDc, HIDc, QKVO, QKVO,
                                       0, 0, 0, 0, 0, 0, 1, 1.0f, 0);
    }

    // 2) RoPE on q and k sections (in place)
    {
        int total = M * 2 * Hh * 64;   // 16,777,216
        rope_kernel<<<total / 256, 256>>>(cosp, sinp);
    }

    // 3) scores[b,h] = scale * Q_bh @ K_bh^T   (NT)
    {
        dim3 grid(Ss / 128, Ss / 128, Bb * Hh);
        const float alpha = 1.0f / sqrtf((float)Dd);
        mma_gemm_kernel<<<grid, 256>>>(nullptr, 1, 0,            // A = q section
                                       nullptr, 1, HIDc,         // B = k section
                                       nullptr, 2, 0,            // C = scores
                                       Ss, Ss, Dd,
                                       QKVO, QKVO, Ss,
                                       (long long)Ss * QKVO, Dd,
                                       (long long)Ss * QKVO, Dd,
                                       (long long)Hh * Ss * Ss, (long long)Ss * Ss,
                                       Hh, alpha, 1);
    }

    // 4) softmax over last axis
    softmax_kernel<<<Bb * Hh * Ss, 256>>>();

    // 5) attn = P_bh @ V_bh   (NN)
    {
        dim3 grid(Dd / 128, Ss / 128, Bb * Hh);
        mma_gemm_kernel<<<grid, 256>>>(nullptr, 2, 0,            // A = scores
                                       nullptr, 1, 2 * HIDc,     // B = v section
                                       nullptr, 3, 0,            // C = attn
                                       Ss, Dd, Ss,
                                       Ss, QKVO, HIDc,
                                       (long long)Hh * Ss * Ss, (long long)Ss * Ss,
                                       (long long)Ss * QKVO, Dd,
                                       (long long)Ss * HIDc, Dd,
                                       Hh, 1.0f, 0);
    }

    // 6) output projection: out = attn @ w_o   (NN)
    {
        dim3 grid(HIDc / 128, M / 128, 1);
        mma_gemm_kernel<<<grid, 256>>>(nullptr, 3, 0, w_o, 0, 0, out, 0, 0,
                                       M, HIDc, HIDc, HIDc, HIDc, HIDc,
                                       0, 0, 0, 0, 0, 0, 1, 1.0f, 0);
    }
}